// round 4
// baseline (speedup 1.0000x reference)
#include <cuda_runtime.h>
#include <math.h>

// Problem constants
#define BB 256
#define SS 512
#define II 128
#define HH 256
#define J4H 1024          // 4*H gate width

// ---------------------------------------------------------------------------
// Scratch (device globals; no cudaMalloc allowed)
// ---------------------------------------------------------------------------
__device__ float g_G[(size_t)BB * SS * J4H];   // 512 MB  precomputed input gates
__device__ float g_Y1[(size_t)BB * SS * HH];   // 128 MB  layer-1 outputs
__device__ float g_H[2][BB * HH];              // double-buffered hidden state
__device__ unsigned g_barCnt;
__device__ volatile unsigned g_barGen;

// ---------------------------------------------------------------------------
// GEMM:  C[n,j] = sum_k A[n,k] * W[j,k] + b1[j] + b2[j]     (J fixed = 1024)
// BM=128, BN=64, BK=16, 256 threads, 8x4 micro-tile
// ---------------------------------------------------------------------------
__global__ __launch_bounds__(256)
void gemm_bias_kernel(const float* __restrict__ A,
                      const float* __restrict__ W,
                      const float* __restrict__ b1,
                      const float* __restrict__ b2,
                      float* __restrict__ C,
                      int K)
{
    const int BM = 128, BN = 64, BK = 16;
    __shared__ float As[16][128];
    __shared__ float Ws[16][64 + 4];

    const int tid = threadIdx.x;
    const int j0 = blockIdx.x * BN;
    const int n0 = blockIdx.y * BM;
    const int tx = tid & 15;        // 16 col-groups of 4
    const int ty = tid >> 4;        // 16 row-groups of 8

    float acc[8][4];
#pragma unroll
    for (int i = 0; i < 8; i++)
#pragma unroll
        for (int j = 0; j < 4; j++) acc[i][j] = 0.f;

    for (int k0 = 0; k0 < K; k0 += BK) {
        // A tile: 128x16 -> 512 float4, 2 per thread, store transposed
#pragma unroll
        for (int i = 0; i < 2; i++) {
            int id  = tid + i * 256;
            int row = id >> 2;
            int kc  = (id & 3) << 2;
            float4 v = *(const float4*)&A[(size_t)(n0 + row) * K + k0 + kc];
            As[kc + 0][row] = v.x;
            As[kc + 1][row] = v.y;
            As[kc + 2][row] = v.z;
            As[kc + 3][row] = v.w;
        }
        // W tile: 64x16 -> 256 float4, 1 per thread
        {
            int row = tid >> 2;
            int kc  = (tid & 3) << 2;
            float4 v = *(const float4*)&W[(size_t)(j0 + row) * K + k0 + kc];
            Ws[kc + 0][row] = v.x;
            Ws[kc + 1][row] = v.y;
            Ws[kc + 2][row] = v.z;
            Ws[kc + 3][row] = v.w;
        }
        __syncthreads();

#pragma unroll
        for (int kk = 0; kk < BK; kk++) {
            float4 a0 = *(const float4*)&As[kk][ty * 8];
            float4 a1 = *(const float4*)&As[kk][ty * 8 + 4];
            float4 wv = *(const float4*)&Ws[kk][tx * 4];
            float a[8] = {a0.x, a0.y, a0.z, a0.w, a1.x, a1.y, a1.z, a1.w};
            float w[4] = {wv.x, wv.y, wv.z, wv.w};
#pragma unroll
            for (int i = 0; i < 8; i++)
#pragma unroll
                for (int j = 0; j < 4; j++) acc[i][j] += a[i] * w[j];
        }
        __syncthreads();
    }

    const int jc = j0 + tx * 4;
    float bsum[4];
#pragma unroll
    for (int j = 0; j < 4; j++) bsum[j] = b1[jc + j] + b2[jc + j];

#pragma unroll
    for (int i = 0; i < 8; i++) {
        int row = n0 + ty * 8 + i;
        float4 o;
        o.x = acc[i][0] + bsum[0];
        o.y = acc[i][1] + bsum[1];
        o.z = acc[i][2] + bsum[2];
        o.w = acc[i][3] + bsum[3];
        *(float4*)&C[(size_t)row * J4H + jc] = o;
    }
}

// ---------------------------------------------------------------------------
// Persistent recurrent kernel.
// Grid = 128 CTAs (16 batch-tiles x 8 h-tiles), 256 threads.
// Each CTA: batches [b0,b0+16), h-cols [h0,h0+32), all 4 gates, K=256.
// W_hh slice (128 rows x 256) in shared; c in registers; h double-buffered
// in global with one grid barrier per time step.
// ---------------------------------------------------------------------------
#define LSTM_NCTA 128
#define WPAD 260                     // row stride: 16B-aligned, stride-4 banks
#define LSTM_SMEM ((128 * WPAD + 16 * 256) * 4)

__device__ __forceinline__ float sigf(float x) {
    return 1.0f / (1.0f + __expf(-x));
}

__device__ __forceinline__ void grid_barrier() {
    __syncthreads();
    if (threadIdx.x == 0) {
        __threadfence();
        unsigned gen = g_barGen;
        if (atomicAdd(&g_barCnt, 1) == LSTM_NCTA - 1) {
            atomicExch(&g_barCnt, 0);
            __threadfence();
            g_barGen = gen + 1;
        } else {
            while (g_barGen == gen) { __nanosleep(32); }
        }
    }
    __syncthreads();
}

__global__ __launch_bounds__(256, 1)
void lstm_layer_kernel(const float* __restrict__ G,
                       const float* __restrict__ Whh,
                       float* __restrict__ Y,
                       float* __restrict__ hOut,
                       float* __restrict__ cOut)
{
    extern __shared__ float sm[];
    float* Wsh = sm;                       // [128][WPAD]
    float* Hsh = sm + 128 * WPAD;          // [16][256]

    const int tid  = threadIdx.x;
    const int hi   = blockIdx.x >> 4;      // 0..7
    const int bi   = blockIdx.x & 15;      // 0..15
    const int h0   = hi * 32;
    const int b0   = bi * 16;
    const int hcol = tid & 31;
    const int bg   = tid >> 5;             // 0..7
    const int col  = h0 + hcol;

    // Load W_hh slice: rows {g*256 + h0 + hh : g in 0..3, hh in 0..31}
    for (int i = tid; i < 128 * 64; i += 256) {
        int row = i >> 6;                  // g*32 + hh
        int kc  = (i & 63) << 2;
        int g   = row >> 5;
        int hh  = row & 31;
        float4 v = *(const float4*)&Whh[(size_t)(g * 256 + h0 + hh) * 256 + kc];
        float* dst = &Wsh[row * WPAD + kc];
        dst[0] = v.x; dst[1] = v.y; dst[2] = v.z; dst[3] = v.w;
    }
    __syncthreads();

    const int bA = b0 + bg * 2;
    const int bB = bA + 1;
    float cA = 0.f, cB = 0.f;
    const float* wI = &Wsh[(0 * 32 + hcol) * WPAD];
    const float* wF = &Wsh[(1 * 32 + hcol) * WPAD];
    const float* wG = &Wsh[(2 * 32 + hcol) * WPAD];
    const float* wO = &Wsh[(3 * 32 + hcol) * WPAD];

    for (int t = 0; t < SS; t++) {
        const size_t nA = (size_t)bA * SS + t;
        const size_t nB = (size_t)bB * SS + t;
        float aI0 = G[nA * J4H + col];
        float aF0 = G[nA * J4H + 256 + col];
        float aG0 = G[nA * J4H + 512 + col];
        float aO0 = G[nA * J4H + 768 + col];
        float aI1 = G[nB * J4H + col];
        float aF1 = G[nB * J4H + 256 + col];
        float aG1 = G[nB * J4H + 512 + col];
        float aO1 = G[nB * J4H + 768 + col];

        if (t > 0) {
            // Stage h_prev tile (16 x 256) into shared; bypass L1 (__ldcg)
            {
                const float* Hprev = g_H[(t - 1) & 1];
                int r = tid >> 4;
                int c = (tid & 15) * 16;
                float4* dsh = (float4*)&Hsh[r * 256 + c];
                const float4* src =
                    (const float4*)&Hprev[(size_t)(b0 + r) * 256 + c];
                dsh[0] = __ldcg(src + 0);
                dsh[1] = __ldcg(src + 1);
                dsh[2] = __ldcg(src + 2);
                dsh[3] = __ldcg(src + 3);
            }
            __syncthreads();

            const float4* hA4 = (const float4*)&Hsh[(bg * 2 + 0) * 256];
            const float4* hB4 = (const float4*)&Hsh[(bg * 2 + 1) * 256];
#pragma unroll 8
            for (int k4 = 0; k4 < 64; k4++) {
                float4 ha = hA4[k4];
                float4 hb = hB4[k4];
                float4 wi = *(const float4*)&wI[k4 * 4];
                float4 wf = *(const float4*)&wF[k4 * 4];
                float4 wg = *(const float4*)&wG[k4 * 4];
                float4 wo = *(const float4*)&wO[k4 * 4];
                aI0 += ha.x * wi.x + ha.y * wi.y + ha.z * wi.z + ha.w * wi.w;
                aF0 += ha.x * wf.x + ha.y * wf.y + ha.z * wf.z + ha.w * wf.w;
                aG0 += ha.x * wg.x + ha.y * wg.y + ha.z * wg.z + ha.w * wg.w;
                aO0 += ha.x * wo.x + ha.y * wo.y + ha.z * wo.z + ha.w * wo.w;
                aI1 += hb.x * wi.x + hb.y * wi.y + hb.z * wi.z + hb.w * wi.w;
                aF1 += hb.x * wf.x + hb.y * wf.y + hb.z * wf.z + hb.w * wf.w;
                aG1 += hb.x * wg.x + hb.y * wg.y + hb.z * wg.z + hb.w * wg.w;
                aO1 += hb.x * wo.x + hb.y * wo.y + hb.z * wo.z + hb.w * wo.w;
            }
        }

        // Gate nonlinearities + state update (torch gate order i,f,g,o)
        float iA = sigf(aI0), fA = sigf(aF0), gA = tanhf(aG0), oA = sigf(aO0);
        cA = fA * cA + iA * gA;
        float hvA = oA * tanhf(cA);
        float iB = sigf(aI1), fB = sigf(aF1), gB = tanhf(aG1), oB = sigf(aO1);
        cB = fB * cB + iB * gB;
        float hvB = oB * tanhf(cB);

        float* Hcur = g_H[t & 1];
        Hcur[(size_t)bA * 256 + col] = hvA;
        Hcur[(size_t)bB * 256 + col] = hvB;
        Y[nA * HH + col] = hvA;
        Y[nB * HH + col] = hvB;
        if (hOut != nullptr && t == SS - 1) {
            hOut[(size_t)bA * 256 + col] = hvA;
            hOut[(size_t)bB * 256 + col] = hvB;
            cOut[(size_t)bA * 256 + col] = cA;
            cOut[(size_t)bB * 256 + col] = cB;
        }

        grid_barrier();
    }
}

// ---------------------------------------------------------------------------
// Launch
// ---------------------------------------------------------------------------
extern "C" void kernel_launch(void* const* d_in, const int* in_sizes, int n_in,
                              void* d_out, int out_size)
{
    (void)in_sizes; (void)n_in; (void)out_size;
    const float* x    = (const float*)d_in[0];
    const float* Wih0 = (const float*)d_in[1];
    const float* Whh0 = (const float*)d_in[2];
    const float* bih0 = (const float*)d_in[3];
    const float* bhh0 = (const float*)d_in[4];
    const float* Wih1 = (const float*)d_in[5];
    const float* Whh1 = (const float*)d_in[6];
    const float* bih1 = (const float*)d_in[7];
    const float* bhh1 = (const float*)d_in[8];

    float* y    = (float*)d_out;                        // [B,S,H]
    float* hOut = y + (size_t)BB * SS * HH;             // [1,B,H]
    float* cOut = hOut + (size_t)BB * HH;               // [1,B,H]

    void *pG = nullptr, *pY1 = nullptr;
    cudaGetSymbolAddress(&pG, g_G);
    cudaGetSymbolAddress(&pY1, g_Y1);

    cudaFuncSetAttribute(lstm_layer_kernel,
                         cudaFuncAttributeMaxDynamicSharedMemorySize,
                         LSTM_SMEM);

    dim3 gemm_grid(J4H / 64, (BB * SS) / 128);

    // Layer 1
    gemm_bias_kernel<<<gemm_grid, 256>>>(x, Wih0, bih0, bhh0, (float*)pG, II);
    lstm_layer_kernel<<<LSTM_NCTA, 256, LSTM_SMEM>>>(
        (const float*)pG, Whh0, (float*)pY1, nullptr, nullptr);

    // Layer 2
    gemm_bias_kernel<<<gemm_grid, 256>>>((const float*)pY1, Wih1, bih1, bhh1,
                                         (float*)pG, HH);
    lstm_layer_kernel<<<LSTM_NCTA, 256, LSTM_SMEM>>>(
        (const float*)pG, Whh1, y, hOut, cOut);
}

// round 7
// speedup vs baseline: 1.6227x; 1.6227x over previous
#include <cuda_runtime.h>
#include <cuda_bf16.h>
#include <math.h>
#include <stdint.h>

// Problem constants
#define BB 256
#define SS 512
#define II 128
#define HH 256
#define J4H 1024          // 4*H gate width

// ---------------------------------------------------------------------------
// Scratch (device globals; no cudaMalloc allowed)
// ---------------------------------------------------------------------------
__device__ float g_G[(size_t)BB * SS * J4H];   // precomputed input gates
__device__ float g_Y1[(size_t)BB * SS * HH];   // layer-1 outputs
__device__ float g_H[2][BB * HH];              // double-buffered hidden state
__device__ unsigned g_barCnt;
__device__ volatile unsigned g_barGen;

// ---------------------------------------------------------------------------
// bf16x3 tensor-core GEMM:
//   C[n,j] = sum_k A[n,k]*W[j,k] + b1[j] + b2[j]     (J fixed = 1024)
// Each fp32 operand is split hi/lo into bf16; three m16n8k16 MMAs emulate
// fp32 precision: Ah*Wh + Al*Wh + Ah*Wl  (error ~2^-16 relative per term).
// BM=128, BN=64, BK=32, 256 threads (8 warps: 4 in m x 2 in n),
// warp tile 32x32 = 2 m-tiles x 4 n-tiles of m16n8k16.
// ---------------------------------------------------------------------------
#define AP 36   // padded row length (bf16 elems) -> 72B rows, ~conflict-free

__global__ __launch_bounds__(256)
void gemm_bias_tc(const float* __restrict__ A,
                  const float* __restrict__ W,
                  const float* __restrict__ b1,
                  const float* __restrict__ b2,
                  float* __restrict__ C,
                  int K)
{
    __shared__ __nv_bfloat16 Ah[128][AP];
    __shared__ __nv_bfloat16 Al[128][AP];
    __shared__ __nv_bfloat16 Wh[64][AP];
    __shared__ __nv_bfloat16 Wl[64][AP];

    const int tid  = threadIdx.x;
    const int lane = tid & 31;
    const int warp = tid >> 5;
    const int wm   = warp & 3;        // 0..3 : 32-row band
    const int wn   = warp >> 2;       // 0..1 : 32-col band
    const int g    = lane >> 2;       // group id 0..7
    const int tg   = lane & 3;        // thread-in-group 0..3

    const int j0 = blockIdx.x * 64;
    const int n0 = blockIdx.y * 128;

    float acc[2][4][4];
#pragma unroll
    for (int mt = 0; mt < 2; mt++)
#pragma unroll
        for (int nt = 0; nt < 4; nt++)
#pragma unroll
            for (int i = 0; i < 4; i++) acc[mt][nt][i] = 0.f;

    // Bias (constant per block-column), hoisted
    float bs[4][2];
#pragma unroll
    for (int nt = 0; nt < 4; nt++) {
        int jc = j0 + wn * 32 + nt * 8 + 2 * tg;
        bs[nt][0] = b1[jc] + b2[jc];
        bs[nt][1] = b1[jc + 1] + b2[jc + 1];
    }

    for (int k0 = 0; k0 < K; k0 += 32) {
        // --- load + split A tile: 128 x 32 fp32 ---
#pragma unroll
        for (int p = 0; p < 4; p++) {
            int id = tid + p * 256;
            int r  = id >> 3;
            int kc = (id & 7) * 4;
            float4 v = *(const float4*)&A[(size_t)(n0 + r) * K + k0 + kc];
            float vv[4] = {v.x, v.y, v.z, v.w};
#pragma unroll
            for (int i = 0; i < 4; i++) {
                __nv_bfloat16 hi = __float2bfloat16(vv[i]);
                Ah[r][kc + i] = hi;
                Al[r][kc + i] = __float2bfloat16(vv[i] - __bfloat162float(hi));
            }
        }
        // --- load + split W tile: 64 x 32 fp32 ---
#pragma unroll
        for (int p = 0; p < 2; p++) {
            int id = tid + p * 256;
            int r  = id >> 3;
            int kc = (id & 7) * 4;
            float4 v = *(const float4*)&W[(size_t)(j0 + r) * K + k0 + kc];
            float vv[4] = {v.x, v.y, v.z, v.w};
#pragma unroll
            for (int i = 0; i < 4; i++) {
                __nv_bfloat16 hi = __float2bfloat16(vv[i]);
                Wh[r][kc + i] = hi;
                Wl[r][kc + i] = __float2bfloat16(vv[i] - __bfloat162float(hi));
            }
        }
        __syncthreads();

#pragma unroll
        for (int ks = 0; ks < 2; ks++) {
            const int c0 = ks * 16 + 2 * tg;   // even -> 4B aligned

            uint32_t ah[2][4], al[2][4];
#pragma unroll
            for (int mt = 0; mt < 2; mt++) {
                int rb = wm * 32 + mt * 16;
                ah[mt][0] = *(const uint32_t*)&Ah[rb + g][c0];
                ah[mt][1] = *(const uint32_t*)&Ah[rb + g + 8][c0];
                ah[mt][2] = *(const uint32_t*)&Ah[rb + g][c0 + 8];
                ah[mt][3] = *(const uint32_t*)&Ah[rb + g + 8][c0 + 8];
                al[mt][0] = *(const uint32_t*)&Al[rb + g][c0];
                al[mt][1] = *(const uint32_t*)&Al[rb + g + 8][c0];
                al[mt][2] = *(const uint32_t*)&Al[rb + g][c0 + 8];
                al[mt][3] = *(const uint32_t*)&Al[rb + g + 8][c0 + 8];
            }
            uint32_t bh[4][2], bl[4][2];
#pragma unroll
            for (int nt = 0; nt < 4; nt++) {
                int jb = wn * 32 + nt * 8 + g;
                bh[nt][0] = *(const uint32_t*)&Wh[jb][c0];
                bh[nt][1] = *(const uint32_t*)&Wh[jb][c0 + 8];
                bl[nt][0] = *(const uint32_t*)&Wl[jb][c0];
                bl[nt][1] = *(const uint32_t*)&Wl[jb][c0 + 8];
            }

#pragma unroll
            for (int mt = 0; mt < 2; mt++)
#pragma unroll
                for (int nt = 0; nt < 4; nt++) {
                    float* c = acc[mt][nt];
#define MMA_BF16(AREG, BREG)                                                   \
    asm volatile(                                                              \
        "mma.sync.aligned.m16n8k16.row.col.f32.bf16.bf16.f32 "                 \
        "{%0,%1,%2,%3}, {%4,%5,%6,%7}, {%8,%9}, {%0,%1,%2,%3};"                \
        : "+f"(c[0]), "+f"(c[1]), "+f"(c[2]), "+f"(c[3])                       \
        : "r"(AREG[0]), "r"(AREG[1]), "r"(AREG[2]), "r"(AREG[3]),              \
          "r"(BREG[0]), "r"(BREG[1]))
                    MMA_BF16(ah[mt], bh[nt]);
                    MMA_BF16(al[mt], bh[nt]);
                    MMA_BF16(ah[mt], bl[nt]);
#undef MMA_BF16
                }
        }
        __syncthreads();
    }

    // Epilogue: c0,c1 -> (row g, cols 2tg,2tg+1); c2,c3 -> (row g+8)
#pragma unroll
    for (int mt = 0; mt < 2; mt++) {
#pragma unroll
        for (int nt = 0; nt < 4; nt++) {
            int r0 = n0 + wm * 32 + mt * 16 + g;
            int jc = j0 + wn * 32 + nt * 8 + 2 * tg;
            float2 o0, o1;
            o0.x = acc[mt][nt][0] + bs[nt][0];
            o0.y = acc[mt][nt][1] + bs[nt][1];
            o1.x = acc[mt][nt][2] + bs[nt][0];
            o1.y = acc[mt][nt][3] + bs[nt][1];
            *(float2*)&C[(size_t)r0 * J4H + jc]       = o0;
            *(float2*)&C[(size_t)(r0 + 8) * J4H + jc] = o1;
        }
    }
}

// ---------------------------------------------------------------------------
// Persistent recurrent kernel (proven datapath from the 17.8ms pass; adds a
// G prefetch so next step's gate loads overlap the grid-barrier spin).
// ---------------------------------------------------------------------------
#define LSTM_NCTA 128
#define WPAD 260
#define LSTM_SMEM ((128 * WPAD + 16 * 256) * 4)

__device__ __forceinline__ float sigf(float x) {
    return 1.0f / (1.0f + __expf(-x));
}

__device__ __forceinline__ void grid_barrier() {
    __syncthreads();
    if (threadIdx.x == 0) {
        __threadfence();
        unsigned gen = g_barGen;
        if (atomicAdd(&g_barCnt, 1) == LSTM_NCTA - 1) {
            atomicExch(&g_barCnt, 0);
            __threadfence();
            g_barGen = gen + 1;
        } else {
            while (g_barGen == gen) { __nanosleep(32); }
        }
    }
    __syncthreads();
}

__global__ __launch_bounds__(256, 1)
void lstm_layer_kernel(const float* __restrict__ G,
                       const float* __restrict__ Whh,
                       float* __restrict__ Y,
                       float* __restrict__ hOut,
                       float* __restrict__ cOut)
{
    extern __shared__ float sm[];
    float* Wsh = sm;                       // [128][WPAD]
    float* Hsh = sm + 128 * WPAD;          // [16][256]

    const int tid  = threadIdx.x;
    const int hi   = blockIdx.x >> 4;      // 0..7
    const int bi   = blockIdx.x & 15;      // 0..15
    const int h0   = hi * 32;
    const int b0   = bi * 16;
    const int hcol = tid & 31;
    const int bg   = tid >> 5;             // 0..7
    const int col  = h0 + hcol;

    for (int i = tid; i < 128 * 64; i += 256) {
        int row = i >> 6;
        int kc  = (i & 63) << 2;
        int g   = row >> 5;
        int hh  = row & 31;
        float4 v = *(const float4*)&Whh[(size_t)(g * 256 + h0 + hh) * 256 + kc];
        float* dst = &Wsh[row * WPAD + kc];
        dst[0] = v.x; dst[1] = v.y; dst[2] = v.z; dst[3] = v.w;
    }
    __syncthreads();

    const int bA = b0 + bg * 2;
    const int bB = bA + 1;
    float cA = 0.f, cB = 0.f;
    const float* wI = &Wsh[(0 * 32 + hcol) * WPAD];
    const float* wF = &Wsh[(1 * 32 + hcol) * WPAD];
    const float* wG = &Wsh[(2 * 32 + hcol) * WPAD];
    const float* wO = &Wsh[(3 * 32 + hcol) * WPAD];

    const size_t gbA = (size_t)bA * SS * J4H + col;   // + t*J4H + gate*256
    const size_t gbB = (size_t)bB * SS * J4H + col;

    // Prefetch t=0 gates
    float nI0 = G[gbA];
    float nF0 = G[gbA + 256];
    float nG0 = G[gbA + 512];
    float nO0 = G[gbA + 768];
    float nI1 = G[gbB];
    float nF1 = G[gbB + 256];
    float nG1 = G[gbB + 512];
    float nO1 = G[gbB + 768];

    for (int t = 0; t < SS; t++) {
        float aI0 = nI0, aF0 = nF0, aG0 = nG0, aO0 = nO0;
        float aI1 = nI1, aF1 = nF1, aG1 = nG1, aO1 = nO1;

        if (t > 0) {
            {
                const float* Hprev = g_H[(t - 1) & 1];
                int r = tid >> 4;
                int c = (tid & 15) * 16;
                float4* dsh = (float4*)&Hsh[r * 256 + c];
                const float4* src =
                    (const float4*)&Hprev[(size_t)(b0 + r) * 256 + c];
                dsh[0] = __ldcg(src + 0);
                dsh[1] = __ldcg(src + 1);
                dsh[2] = __ldcg(src + 2);
                dsh[3] = __ldcg(src + 3);
            }
            __syncthreads();

            const float4* hA4 = (const float4*)&Hsh[(bg * 2 + 0) * 256];
            const float4* hB4 = (const float4*)&Hsh[(bg * 2 + 1) * 256];
#pragma unroll 8
            for (int k4 = 0; k4 < 64; k4++) {
                float4 ha = hA4[k4];
                float4 hb = hB4[k4];
                float4 wi = *(const float4*)&wI[k4 * 4];
                float4 wf = *(const float4*)&wF[k4 * 4];
                float4 wg = *(const float4*)&wG[k4 * 4];
                float4 wo = *(const float4*)&wO[k4 * 4];
                aI0 += ha.x * wi.x + ha.y * wi.y + ha.z * wi.z + ha.w * wi.w;
                aF0 += ha.x * wf.x + ha.y * wf.y + ha.z * wf.z + ha.w * wf.w;
                aG0 += ha.x * wg.x + ha.y * wg.y + ha.z * wg.z + ha.w * wg.w;
                aO0 += ha.x * wo.x + ha.y * wo.y + ha.z * wo.z + ha.w * wo.w;
                aI1 += hb.x * wi.x + hb.y * wi.y + hb.z * wi.z + hb.w * wi.w;
                aF1 += hb.x * wf.x + hb.y * wf.y + hb.z * wf.z + hb.w * wf.w;
                aG1 += hb.x * wg.x + hb.y * wg.y + hb.z * wg.z + hb.w * wg.w;
                aO1 += hb.x * wo.x + hb.y * wo.y + hb.z * wo.z + hb.w * wo.w;
            }
        }

        float iA = sigf(aI0), fA = sigf(aF0), gA = tanhf(aG0), oA = sigf(aO0);
        cA = fA * cA + iA * gA;
        float hvA = oA * tanhf(cA);
        float iB = sigf(aI1), fB = sigf(aF1), gB = tanhf(aG1), oB = sigf(aO1);
        cB = fB * cB + iB * gB;
        float hvB = oB * tanhf(cB);

        float* Hcur = g_H[t & 1];
        Hcur[(size_t)bA * 256 + col] = hvA;
        Hcur[(size_t)bB * 256 + col] = hvB;
        const size_t nA = (size_t)bA * SS + t;
        const size_t nB = (size_t)bB * SS + t;
        Y[nA * HH + col] = hvA;
        Y[nB * HH + col] = hvB;
        if (hOut != nullptr && t == SS - 1) {
            hOut[(size_t)bA * 256 + col] = hvA;
            hOut[(size_t)bB * 256 + col] = hvB;
            cOut[(size_t)bA * 256 + col] = cA;
            cOut[(size_t)bB * 256 + col] = cB;
        }

        // Prefetch next step's gates BEFORE the barrier: the LDG latency
        // overlaps the barrier arrival/spin instead of serializing after it.
        if (t + 1 < SS) {
            size_t oA2 = gbA + (size_t)(t + 1) * J4H;
            size_t oB2 = gbB + (size_t)(t + 1) * J4H;
            nI0 = G[oA2];       nF0 = G[oA2 + 256];
            nG0 = G[oA2 + 512]; nO0 = G[oA2 + 768];
            nI1 = G[oB2];       nF1 = G[oB2 + 256];
            nG1 = G[oB2 + 512]; nO1 = G[oB2 + 768];
        }

        grid_barrier();
    }
}

// ---------------------------------------------------------------------------
// Launch
// ---------------------------------------------------------------------------
extern "C" void kernel_launch(void* const* d_in, const int* in_sizes, int n_in,
                              void* d_out, int out_size)
{
    (void)in_sizes; (void)n_in; (void)out_size;
    const float* x    = (const float*)d_in[0];
    const float* Wih0 = (const float*)d_in[1];
    const float* Whh0 = (const float*)d_in[2];
    const float* bih0 = (const float*)d_in[3];
    const float* bhh0 = (const float*)d_in[4];
    const float* Wih1 = (const float*)d_in[5];
    const float* Whh1 = (const float*)d_in[6];
    const float* bih1 = (const float*)d_in[7];
    const float* bhh1 = (const float*)d_in[8];

    float* y    = (float*)d_out;                        // [B,S,H]
    float* hOut = y + (size_t)BB * SS * HH;             // [1,B,H]
    float* cOut = hOut + (size_t)BB * HH;               // [1,B,H]

    void *pG = nullptr, *pY1 = nullptr;
    cudaGetSymbolAddress(&pG, g_G);
    cudaGetSymbolAddress(&pY1, g_Y1);

    cudaFuncSetAttribute(lstm_layer_kernel,
                         cudaFuncAttributeMaxDynamicSharedMemorySize,
                         LSTM_SMEM);

    dim3 gemm_grid(J4H / 64, (BB * SS) / 128);

    // Layer 1
    gemm_bias_tc<<<gemm_grid, 256>>>(x, Wih0, bih0, bhh0, (float*)pG, II);
    lstm_layer_kernel<<<LSTM_NCTA, 256, LSTM_SMEM>>>(
        (const float*)pG, Whh0, (float*)pY1, nullptr, nullptr);

    // Layer 2
    gemm_bias_tc<<<gemm_grid, 256>>>((const float*)pY1, Wih1, bih1, bhh1,
                                     (float*)pG, HH);
    lstm_layer_kernel<<<LSTM_NCTA, 256, LSTM_SMEM>>>(
        (const float*)pG, Whh1, y, hOut, cOut);
}

// round 9
// speedup vs baseline: 2.1434x; 1.3209x over previous
#include <cuda_runtime.h>
#include <cuda_bf16.h>
#include <math.h>
#include <stdint.h>

// Problem constants
#define BB 256
#define SS 512
#define II 128
#define HH 256
#define J4H 1024          // 4*H gate width

// ---------------------------------------------------------------------------
// Scratch (device globals; no cudaMalloc allowed)
// ---------------------------------------------------------------------------
__device__ float g_G[(size_t)BB * SS * J4H];   // precomputed input gates
__device__ float g_Y1[(size_t)BB * SS * HH];   // layer-1 outputs
__device__ __nv_bfloat16 g_Hh[2][BB * HH];     // hidden state hi (bf16), 2 buf
__device__ __nv_bfloat16 g_Hl[2][BB * HH];     // hidden state lo (bf16), 2 buf

// ---------------------------------------------------------------------------
// bf16x3 tensor-core GEMM (unchanged from the 10.97ms pass):
//   C[n,j] = sum_k A[n,k]*W[j,k] + b1[j] + b2[j]     (J fixed = 1024)
// ---------------------------------------------------------------------------
#define AP 36

#define MMA_BF16(CREG, AREG, BREG)                                             \
    asm volatile(                                                              \
        "mma.sync.aligned.m16n8k16.row.col.f32.bf16.bf16.f32 "                 \
        "{%0,%1,%2,%3}, {%4,%5,%6,%7}, {%8,%9}, {%0,%1,%2,%3};"                \
        : "+f"(CREG[0]), "+f"(CREG[1]), "+f"(CREG[2]), "+f"(CREG[3])           \
        : "r"(AREG[0]), "r"(AREG[1]), "r"(AREG[2]), "r"(AREG[3]),              \
          "r"(BREG[0]), "r"(BREG[1]))

__global__ __launch_bounds__(256)
void gemm_bias_tc(const float* __restrict__ A,
                  const float* __restrict__ W,
                  const float* __restrict__ b1,
                  const float* __restrict__ b2,
                  float* __restrict__ C,
                  int K)
{
    __shared__ __nv_bfloat16 Ah[128][AP];
    __shared__ __nv_bfloat16 Al[128][AP];
    __shared__ __nv_bfloat16 Wh[64][AP];
    __shared__ __nv_bfloat16 Wl[64][AP];

    const int tid  = threadIdx.x;
    const int lane = tid & 31;
    const int warp = tid >> 5;
    const int wm   = warp & 3;
    const int wn   = warp >> 2;
    const int g    = lane >> 2;
    const int tg   = lane & 3;

    const int j0 = blockIdx.x * 64;
    const int n0 = blockIdx.y * 128;

    float acc[2][4][4];
#pragma unroll
    for (int mt = 0; mt < 2; mt++)
#pragma unroll
        for (int nt = 0; nt < 4; nt++)
#pragma unroll
            for (int i = 0; i < 4; i++) acc[mt][nt][i] = 0.f;

    float bs[4][2];
#pragma unroll
    for (int nt = 0; nt < 4; nt++) {
        int jc = j0 + wn * 32 + nt * 8 + 2 * tg;
        bs[nt][0] = b1[jc] + b2[jc];
        bs[nt][1] = b1[jc + 1] + b2[jc + 1];
    }

    for (int k0 = 0; k0 < K; k0 += 32) {
#pragma unroll
        for (int p = 0; p < 4; p++) {
            int id = tid + p * 256;
            int r  = id >> 3;
            int kc = (id & 7) * 4;
            float4 v = *(const float4*)&A[(size_t)(n0 + r) * K + k0 + kc];
            float vv[4] = {v.x, v.y, v.z, v.w};
#pragma unroll
            for (int i = 0; i < 4; i++) {
                __nv_bfloat16 hi = __float2bfloat16(vv[i]);
                Ah[r][kc + i] = hi;
                Al[r][kc + i] = __float2bfloat16(vv[i] - __bfloat162float(hi));
            }
        }
#pragma unroll
        for (int p = 0; p < 2; p++) {
            int id = tid + p * 256;
            int r  = id >> 3;
            int kc = (id & 7) * 4;
            float4 v = *(const float4*)&W[(size_t)(j0 + r) * K + k0 + kc];
            float vv[4] = {v.x, v.y, v.z, v.w};
#pragma unroll
            for (int i = 0; i < 4; i++) {
                __nv_bfloat16 hi = __float2bfloat16(vv[i]);
                Wh[r][kc + i] = hi;
                Wl[r][kc + i] = __float2bfloat16(vv[i] - __bfloat162float(hi));
            }
        }
        __syncthreads();

#pragma unroll
        for (int ks = 0; ks < 2; ks++) {
            const int c0 = ks * 16 + 2 * tg;

            uint32_t ah[2][4], al[2][4];
#pragma unroll
            for (int mt = 0; mt < 2; mt++) {
                int rb = wm * 32 + mt * 16;
                ah[mt][0] = *(const uint32_t*)&Ah[rb + g][c0];
                ah[mt][1] = *(const uint32_t*)&Ah[rb + g + 8][c0];
                ah[mt][2] = *(const uint32_t*)&Ah[rb + g][c0 + 8];
                ah[mt][3] = *(const uint32_t*)&Ah[rb + g + 8][c0 + 8];
                al[mt][0] = *(const uint32_t*)&Al[rb + g][c0];
                al[mt][1] = *(const uint32_t*)&Al[rb + g + 8][c0];
                al[mt][2] = *(const uint32_t*)&Al[rb + g][c0 + 8];
                al[mt][3] = *(const uint32_t*)&Al[rb + g + 8][c0 + 8];
            }
            uint32_t bh[4][2], bl[4][2];
#pragma unroll
            for (int nt = 0; nt < 4; nt++) {
                int jb = wn * 32 + nt * 8 + g;
                bh[nt][0] = *(const uint32_t*)&Wh[jb][c0];
                bh[nt][1] = *(const uint32_t*)&Wh[jb][c0 + 8];
                bl[nt][0] = *(const uint32_t*)&Wl[jb][c0];
                bl[nt][1] = *(const uint32_t*)&Wl[jb][c0 + 8];
            }

#pragma unroll
            for (int mt = 0; mt < 2; mt++)
#pragma unroll
                for (int nt = 0; nt < 4; nt++) {
                    float* c = acc[mt][nt];
                    MMA_BF16(c, ah[mt], bh[nt]);
                    MMA_BF16(c, al[mt], bh[nt]);
                    MMA_BF16(c, ah[mt], bl[nt]);
                }
        }
        __syncthreads();
    }

#pragma unroll
    for (int mt = 0; mt < 2; mt++) {
#pragma unroll
        for (int nt = 0; nt < 4; nt++) {
            int r0 = n0 + wm * 32 + mt * 16 + g;
            int jc = j0 + wn * 32 + nt * 8 + 2 * tg;
            float2 o0, o1;
            o0.x = acc[mt][nt][0] + bs[nt][0];
            o0.y = acc[mt][nt][1] + bs[nt][1];
            o1.x = acc[mt][nt][2] + bs[nt][0];
            o1.y = acc[mt][nt][3] + bs[nt][1];
            *(float2*)&C[(size_t)r0 * J4H + jc]       = o0;
            *(float2*)&C[(size_t)(r0 + 8) * J4H + jc] = o1;
        }
    }
}

// ---------------------------------------------------------------------------
// Tensor-core recurrent kernel.
// Grid = 128 CTAs as 16 clusters of 8. Cluster c owns batch [16c,16c+16).
// CTA rank r owns h-cols [32r,32r+32) x 4 gates = local n in [0,128):
//   n = g4*32 + jl  (g4 = gate i/f/g/o, jl = h-col within band)
// Per step: acc[16,128] = Hprev[16,256] @ WhhSlice^T  via bf16x3 MMA,
// k split over warp halves (warps 0-3: k<128, warps 4-7: k>=128),
// smem reduction, per-thread epilogue with register cell state.
// Sync: hardware cluster barrier (release/acquire orders global h stores).
// ---------------------------------------------------------------------------
#define WPITCH 264        // bf16 elems per smem row (528B, conflict-free)
#define GPITCH 132        // fp32 elems per gate-smem row
// byte offsets in dynamic smem
#define SM_WH    0
#define SM_WL    (SM_WH + 128 * WPITCH * 2)          // 67584
#define SM_HH    (SM_WL + 128 * WPITCH * 2)          // 135168
#define SM_HL    (SM_HH + 16 * WPITCH * 2)           // 143616
#define SM_PART  (SM_HL + 16 * WPITCH * 2)           // 152064
#define SM_GATES (SM_PART + 16 * GPITCH * 4)         // 160512
#define LSTM2_SMEM (SM_GATES + 16 * GPITCH * 4)      // 168960

__device__ __forceinline__ float sigf(float x) {
    return 1.0f / (1.0f + __expf(-x));
}
__device__ __forceinline__ float tanhfast(float x) {
    return 2.0f / (1.0f + __expf(-2.0f * x)) - 1.0f;
}

__global__ __launch_bounds__(256, 1) __cluster_dims__(8, 1, 1)
void lstm_tc_kernel(const float* __restrict__ G,
                    const float* __restrict__ Whh,
                    float* __restrict__ Y,
                    float* __restrict__ hOut,
                    float* __restrict__ cOut)
{
    extern __shared__ char smraw[];
    __nv_bfloat16* WhS = (__nv_bfloat16*)(smraw + SM_WH);
    __nv_bfloat16* WlS = (__nv_bfloat16*)(smraw + SM_WL);
    __nv_bfloat16* HhS = (__nv_bfloat16*)(smraw + SM_HH);
    __nv_bfloat16* HlS = (__nv_bfloat16*)(smraw + SM_HL);
    float* SmPart  = (float*)(smraw + SM_PART);
    float* SmGates = (float*)(smraw + SM_GATES);

    const int tid   = threadIdx.x;
    const int lane  = tid & 31;
    const int warp  = tid >> 5;
    const int g     = lane >> 2;       // 0..7
    const int tg    = lane & 3;        // 0..3
    const int kh    = warp >> 2;       // k-half: 0 or 1
    const int nw    = warp & 3;        // n-band = gate block 0..3
    const int rank  = blockIdx.x & 7;  // cluster CTA rank -> h band
    const int cid   = blockIdx.x >> 3; // cluster id -> batch tile
    const int b0    = cid * 16;
    const int hbase = rank * 32;

    // ---- Load + split Whh slice: 128 rows (g4*256 + hbase + jl) x 256 k ----
    for (int i = tid; i < 128 * 64; i += 256) {
        int row = i >> 6;              // local n = g4*32 + jl
        int kc  = (i & 63) * 4;
        int g4  = row >> 5;
        int jl  = row & 31;
        float4 v = *(const float4*)
            &Whh[(size_t)(g4 * 256 + hbase + jl) * 256 + kc];
        float vv[4] = {v.x, v.y, v.z, v.w};
#pragma unroll
        for (int ii = 0; ii < 4; ii++) {
            __nv_bfloat16 hi = __float2bfloat16(vv[ii]);
            WhS[row * WPITCH + kc + ii] = hi;
            WlS[row * WPITCH + kc + ii] =
                __float2bfloat16(vv[ii] - __bfloat162float(hi));
        }
    }
    __syncthreads();

    // ---- Per-thread ownership for epilogue: 2 (b, jl) pairs ----
    int bP[2], jlP[2];
    size_t gofs[2], yofs[2], hofs[2];
#pragma unroll
    for (int pp = 0; pp < 2; pp++) {
        int id = tid + 256 * pp;       // 0..511
        bP[pp]  = id >> 5;             // 0..15
        jlP[pp] = id & 31;
        gofs[pp] = ((size_t)(b0 + bP[pp]) * SS) * J4H + hbase + jlP[pp];
        yofs[pp] = ((size_t)(b0 + bP[pp]) * SS) * HH + hbase + jlP[pp];
        hofs[pp] = (size_t)(b0 + bP[pp]) * HH + hbase + jlP[pp];
    }
    float cS[2] = {0.f, 0.f};

    // Prefetch t=0 gate inputs
    float pre[2][4];
#pragma unroll
    for (int pp = 0; pp < 2; pp++)
#pragma unroll
        for (int g4 = 0; g4 < 4; g4++)
            pre[pp][g4] = __ldcg(&G[gofs[pp] + g4 * 256]);

    const int kbase = kh * 128;

    for (int t = 0; t < SS; t++) {
        if (t > 0) {
            // ---- Stage h(t-1) tile: 16 x 256 hi/lo bf16 into smem ----
            {
                const int rb = (t - 1) & 1;
                int r = tid >> 4;
                int q = tid & 15;
                const uint4* sH = (const uint4*)&g_Hh[rb][(size_t)(b0 + r) * HH];
                const uint4* sL = (const uint4*)&g_Hl[rb][(size_t)(b0 + r) * HH];
                *(uint4*)&HhS[r * WPITCH + 8 * q]        = __ldcg(sH + q);
                *(uint4*)&HhS[r * WPITCH + 8 * q + 128]  = __ldcg(sH + q + 16);
                *(uint4*)&HlS[r * WPITCH + 8 * q]        = __ldcg(sL + q);
                *(uint4*)&HlS[r * WPITCH + 8 * q + 128]  = __ldcg(sL + q + 16);
            }
            __syncthreads();

            // ---- MMA: acc[16 x 32band] over this warp's k-half ----
            float acc[4][4];
#pragma unroll
            for (int nt = 0; nt < 4; nt++)
#pragma unroll
                for (int i = 0; i < 4; i++) acc[nt][i] = 0.f;

#pragma unroll
            for (int kt = 0; kt < 8; kt++) {
                const int c0 = kbase + kt * 16 + 2 * tg;
                uint32_t ah[4], al[4];
                ah[0] = *(const uint32_t*)&HhS[g * WPITCH + c0];
                ah[1] = *(const uint32_t*)&HhS[(g + 8) * WPITCH + c0];
                ah[2] = *(const uint32_t*)&HhS[g * WPITCH + c0 + 8];
                ah[3] = *(const uint32_t*)&HhS[(g + 8) * WPITCH + c0 + 8];
                al[0] = *(const uint32_t*)&HlS[g * WPITCH + c0];
                al[1] = *(const uint32_t*)&HlS[(g + 8) * WPITCH + c0];
                al[2] = *(const uint32_t*)&HlS[g * WPITCH + c0 + 8];
                al[3] = *(const uint32_t*)&HlS[(g + 8) * WPITCH + c0 + 8];
#pragma unroll
                for (int nt = 0; nt < 4; nt++) {
                    int jb = 32 * nw + 8 * nt + g;
                    uint32_t bh[2], bl[2];
                    bh[0] = *(const uint32_t*)&WhS[jb * WPITCH + c0];
                    bh[1] = *(const uint32_t*)&WhS[jb * WPITCH + c0 + 8];
                    bl[0] = *(const uint32_t*)&WlS[jb * WPITCH + c0];
                    bl[1] = *(const uint32_t*)&WlS[jb * WPITCH + c0 + 8];
                    float* c = acc[nt];
                    MMA_BF16(c, ah, bh);
                    MMA_BF16(c, al, bh);
                    MMA_BF16(c, ah, bl);
                }
            }

            // ---- k-reduction through smem ----
            if (kh == 1) {
#pragma unroll
                for (int nt = 0; nt < 4; nt++) {
                    int col = 32 * nw + 8 * nt + 2 * tg;
                    SmPart[g * GPITCH + col]           = acc[nt][0];
                    SmPart[g * GPITCH + col + 1]       = acc[nt][1];
                    SmPart[(g + 8) * GPITCH + col]     = acc[nt][2];
                    SmPart[(g + 8) * GPITCH + col + 1] = acc[nt][3];
                }
            }
            __syncthreads();
            if (kh == 0) {
#pragma unroll
                for (int nt = 0; nt < 4; nt++) {
                    int col = 32 * nw + 8 * nt + 2 * tg;
                    SmGates[g * GPITCH + col] =
                        acc[nt][0] + SmPart[g * GPITCH + col];
                    SmGates[g * GPITCH + col + 1] =
                        acc[nt][1] + SmPart[g * GPITCH + col + 1];
                    SmGates[(g + 8) * GPITCH + col] =
                        acc[nt][2] + SmPart[(g + 8) * GPITCH + col];
                    SmGates[(g + 8) * GPITCH + col + 1] =
                        acc[nt][3] + SmPart[(g + 8) * GPITCH + col + 1];
                }
            }
            __syncthreads();
        }

        // ---- Epilogue: gates -> nonlinearity -> state -> stores ----
        const int wb = t & 1;
#pragma unroll
        for (int pp = 0; pp < 2; pp++) {
            float gi = pre[pp][0], gf = pre[pp][1];
            float gg = pre[pp][2], go = pre[pp][3];
            if (t > 0) {
                const float* row = &SmGates[bP[pp] * GPITCH + jlP[pp]];
                gi += row[0];
                gf += row[32];
                gg += row[64];
                go += row[96];
            }
            float iv = sigf(gi), fv = sigf(gf);
            float gv = tanhfast(gg), ov = sigf(go);
            cS[pp] = fv * cS[pp] + iv * gv;
            float hv = ov * tanhfast(cS[pp]);

            Y[yofs[pp] + (size_t)t * HH] = hv;
            __nv_bfloat16 hi = __float2bfloat16(hv);
            g_Hh[wb][hofs[pp]] = hi;
            g_Hl[wb][hofs[pp]] =
                __float2bfloat16(hv - __bfloat162float(hi));
            if (hOut != nullptr && t == SS - 1) {
                hOut[hofs[pp]] = hv;
                cOut[hofs[pp]] = cS[pp];
            }
        }

        // ---- Prefetch next step's G (overlaps barrier latency) ----
        if (t + 1 < SS) {
#pragma unroll
            for (int pp = 0; pp < 2; pp++)
#pragma unroll
                for (int g4 = 0; g4 < 4; g4++)
                    pre[pp][g4] =
                        __ldcg(&G[gofs[pp] + (size_t)(t + 1) * J4H + g4 * 256]);
        }

        // ---- Cluster barrier: release h stores, acquire peers' ----
        asm volatile("barrier.cluster.arrive.aligned;" ::: "memory");
        asm volatile("barrier.cluster.wait.aligned;" ::: "memory");
    }
}

// ---------------------------------------------------------------------------
// Launch
// ---------------------------------------------------------------------------
extern "C" void kernel_launch(void* const* d_in, const int* in_sizes, int n_in,
                              void* d_out, int out_size)
{
    (void)in_sizes; (void)n_in; (void)out_size;
    const float* x    = (const float*)d_in[0];
    const float* Wih0 = (const float*)d_in[1];
    const float* Whh0 = (const float*)d_in[2];
    const float* bih0 = (const float*)d_in[3];
    const float* bhh0 = (const float*)d_in[4];
    const float* Wih1 = (const float*)d_in[5];
    const float* Whh1 = (const float*)d_in[6];
    const float* bih1 = (const float*)d_in[7];
    const float* bhh1 = (const float*)d_in[8];

    float* y    = (float*)d_out;                        // [B,S,H]
    float* hOut = y + (size_t)BB * SS * HH;             // [1,B,H]
    float* cOut = hOut + (size_t)BB * HH;               // [1,B,H]

    void *pG = nullptr, *pY1 = nullptr;
    cudaGetSymbolAddress(&pG, g_G);
    cudaGetSymbolAddress(&pY1, g_Y1);

    cudaFuncSetAttribute(lstm_tc_kernel,
                         cudaFuncAttributeMaxDynamicSharedMemorySize,
                         LSTM2_SMEM);

    dim3 gemm_grid(J4H / 64, (BB * SS) / 128);

    // Layer 1
    gemm_bias_tc<<<gemm_grid, 256>>>(x, Wih0, bih0, bhh0, (float*)pG, II);
    lstm_tc_kernel<<<128, 256, LSTM2_SMEM>>>(
        (const float*)pG, Whh0, (float*)pY1, nullptr, nullptr);

    // Layer 2
    gemm_bias_tc<<<gemm_grid, 256>>>((const float*)pY1, Wih1, bih1, bhh1,
                                     (float*)pG, HH);
    lstm_tc_kernel<<<128, 256, LSTM2_SMEM>>>(
        (const float*)pG, Whh1, y, hOut, cOut);
}